// round 7
// baseline (speedup 1.0000x reference)
#include <cuda_runtime.h>
#include <cuda_fp16.h>
#include <cuda_bf16.h>
#include <math.h>
#include <stdint.h>

// Problem constants
#define BB 512   // batch
#define DD 512   // input dim / columns
#define LL 32    // latent
#define HH 300   // hidden
#define MT 128   // batch tile (M) in decoder
#define NP 320   // padded N (40 tiles of 8)
#define RS 328   // padded row stride (halves) for W1/W2/G1
#define KT 19    // k16-chunks in gemm2
#define ZS 40    // Zms stride in halves
#define NTHR 640 // decoder threads (20 warps = 4m x 5n)
#define CHUNK_H (16 * RS)          // halves per W2 chunk = 5248
#define CHUNK_B (CHUNK_H * 2)      // bytes per chunk = 10496
#define CHUNK_U (CHUNK_B / 16)     // 16B units = 656
#define W1_U    (2 * CHUNK_U)      // W1 = 32 x RS = 1312 units

// SMEM layout (bytes): Zms | G1s | W1s | ring(5) | outs
#define SO_ZM   0
#define SO_G1   10240                     // 128*40*2
#define SO_W1   (SO_G1 + MT * RS * 2)     // 10240 + 83968 = 94208
#define SO_RING (SO_W1 + 32 * RS * 2)     // 94208 + 20992 = 115200
#define SO_OUT  (SO_RING + 5 * CHUNK_B)   // 115200 + 52480 = 167680
#define SMEM_TOTAL (SO_OUT + MT * 4)      // 168192

// ---------------------------------------------------------------------------
// Scratch (device globals: allocation-free rule)
// ---------------------------------------------------------------------------
__device__ float g_h1[BB * HH];
__device__ float g_h2[BB * HH];
__device__ float g_z[BB * LL];
__device__ __half g_w1h[LL * RS];          // [32][328] fp16, padded
__device__ __half g_w2h[KT * CHUNK_H];     // [19][16][328] fp16, chunk-contiguous

// ---------------------------------------------------------------------------
// PTX helpers
// ---------------------------------------------------------------------------
__device__ __forceinline__ void ldsm_x4(uint32_t* r, uint32_t addr) {
    asm volatile("ldmatrix.sync.aligned.m8n8.x4.shared.b16 {%0,%1,%2,%3}, [%4];"
                 : "=r"(r[0]), "=r"(r[1]), "=r"(r[2]), "=r"(r[3]) : "r"(addr));
}
__device__ __forceinline__ void ldsm_x4t(uint32_t* r, uint32_t addr) {
    asm volatile("ldmatrix.sync.aligned.m8n8.x4.trans.shared.b16 {%0,%1,%2,%3}, [%4];"
                 : "=r"(r[0]), "=r"(r[1]), "=r"(r[2]), "=r"(r[3]) : "r"(addr));
}
__device__ __forceinline__ void mma16(float* d, const uint32_t* a, uint32_t b0, uint32_t b1) {
    asm volatile(
        "mma.sync.aligned.m16n8k16.row.col.f32.f16.f16.f32 "
        "{%0,%1,%2,%3}, {%4,%5,%6,%7}, {%8,%9}, {%0,%1,%2,%3};"
        : "+f"(d[0]), "+f"(d[1]), "+f"(d[2]), "+f"(d[3])
        : "r"(a[0]), "r"(a[1]), "r"(a[2]), "r"(a[3]), "r"(b0), "r"(b1));
}
__device__ __forceinline__ void cp16(uint32_t dst, const void* src) {
    asm volatile("cp.async.cg.shared.global [%0], [%1], 16;" :: "r"(dst), "l"(src));
}
__device__ __forceinline__ void cp_commit() {
    asm volatile("cp.async.commit_group;");
}

// ---------------------------------------------------------------------------
// Pack weights to fp16 padded layouts
// ---------------------------------------------------------------------------
__global__ void pack_weights(const float* __restrict__ gen_w1,
                             const float* __restrict__ gen_w2) {
    int idx = blockIdx.x * blockDim.x + threadIdx.x;
    if (idx < LL * RS) {
        int r = idx / RS, c = idx % RS;
        g_w1h[idx] = (c < HH) ? __float2half(gen_w1[r * HH + c]) : __half(0.f);
    } else {
        int i2 = idx - LL * RS;
        if (i2 < KT * CHUNK_H) {
            int k = i2 / RS, c = i2 % RS;
            g_w2h[i2] = (k < HH && c < HH) ? __float2half(gen_w2[k * HH + c])
                                           : __half(0.f);
        }
    }
}

// ---------------------------------------------------------------------------
// Encoder SGEMM with bias + relu
// ---------------------------------------------------------------------------
__global__ void gemm_bias_relu(const float* __restrict__ A,
                               const float* __restrict__ Bw,
                               const float* __restrict__ bias,
                               float* __restrict__ C,
                               int M, int N, int K) {
    const int BK = 8;
    __shared__ float As[BK][64];
    __shared__ float Bs[BK][64];
    int tid = threadIdx.x;
    int tx = tid % 16, ty = tid / 16;
    int rowBase = blockIdx.y * 64;
    int colBase = blockIdx.x * 64;
    float acc[4][4] = {};
    for (int k0 = 0; k0 < K; k0 += BK) {
        #pragma unroll
        for (int i = 0; i < 2; i++) {
            int idx = tid * 2 + i;
            int r = idx / BK, kk = idx % BK;
            int gr = rowBase + r, gk = k0 + kk;
            As[kk][r] = (gr < M && gk < K) ? A[gr * K + gk] : 0.f;
        }
        #pragma unroll
        for (int i = 0; i < 2; i++) {
            int idx = tid * 2 + i;
            int kk = idx / 64, c = idx % 64;
            int gc = colBase + c, gk = k0 + kk;
            Bs[kk][c] = (gc < N && gk < K) ? Bw[gk * N + gc] : 0.f;
        }
        __syncthreads();
        #pragma unroll
        for (int kk = 0; kk < BK; kk++) {
            float a[4], b[4];
            #pragma unroll
            for (int i = 0; i < 4; i++) a[i] = As[kk][ty * 4 + i];
            #pragma unroll
            for (int jj = 0; jj < 4; jj++) b[jj] = Bs[kk][tx * 4 + jj];
            #pragma unroll
            for (int i = 0; i < 4; i++)
                #pragma unroll
                for (int jj = 0; jj < 4; jj++)
                    acc[i][jj] += a[i] * b[jj];
        }
        __syncthreads();
    }
    #pragma unroll
    for (int i = 0; i < 4; i++) {
        int r = rowBase + ty * 4 + i;
        if (r >= M) continue;
        #pragma unroll
        for (int jj = 0; jj < 4; jj++) {
            int c = colBase + tx * 4 + jj;
            if (c >= N) continue;
            float v = acc[i][jj] + bias[c];
            C[r * N + c] = v > 0.f ? v : 0.f;
        }
    }
}

// ---------------------------------------------------------------------------
// Heads, split-K: warp (b_loc, q) partials over h in [75q, 75q+75).
// Block = 256 threads = 2 batches x 4 quarters. Grid = 256 blocks.
// ---------------------------------------------------------------------------
__global__ void heads_kernel(const float* __restrict__ zm_w,
                             const float* __restrict__ zm_b,
                             const float* __restrict__ zl_w,
                             const float* __restrict__ zl_b,
                             const float* __restrict__ eps,
                             float* __restrict__ z_out,
                             float* __restrict__ zm_out,
                             float* __restrict__ zl_out) {
    __shared__ float pam[8][32], pal[8][32];
    int lane = threadIdx.x & 31;
    int w = threadIdx.x >> 5;
    int b = blockIdx.x * 2 + (w >> 2);
    int q = w & 3;
    const float* h2row = g_h2 + b * HH;
    int h0 = q * 75;
    float am0 = 0.f, am1 = 0.f, am2 = 0.f;
    float al0 = 0.f, al1 = 0.f, al2 = 0.f;
    #pragma unroll 5
    for (int h = h0; h < h0 + 75; h += 3) {
        float v0 = __ldg(h2row + h);
        float v1 = __ldg(h2row + h + 1);
        float v2 = __ldg(h2row + h + 2);
        am0 += v0 * __ldg(zm_w + (h    ) * LL + lane);
        am1 += v1 * __ldg(zm_w + (h + 1) * LL + lane);
        am2 += v2 * __ldg(zm_w + (h + 2) * LL + lane);
        al0 += v0 * __ldg(zl_w + (h    ) * LL + lane);
        al1 += v1 * __ldg(zl_w + (h + 1) * LL + lane);
        al2 += v2 * __ldg(zl_w + (h + 2) * LL + lane);
    }
    pam[w][lane] = am0 + am1 + am2;
    pal[w][lane] = al0 + al1 + al2;
    __syncthreads();
    if (q == 0) {
        float am = pam[w][lane] + pam[w + 1][lane] + pam[w + 2][lane]
                 + pam[w + 3][lane] + zm_b[lane];
        float al = pal[w][lane] + pal[w + 1][lane] + pal[w + 2][lane]
                 + pal[w + 3][lane] + zl_b[lane];
        int o = b * LL + lane;
        float zv = am + eps[o] * expf(0.5f * al);
        zm_out[o] = am;
        zl_out[o] = al;
        z_out[o]  = zv;
        g_z[o]    = zv;
    }
}

// ---------------------------------------------------------------------------
// fp16 mma.sync fused decoder. CTA = (column j, 128-batch tile).
// 640 threads = 20 warps: warp & 3 -> m 32-row stripe (2 m16 tiles),
//                         warp >> 2 -> n-group (8 n8-tiles).
// 5-stage W2 ring, prefetch distance 3 chunks.
// ---------------------------------------------------------------------------
__global__ void __launch_bounds__(NTHR, 1)
decoder_kernel(const float* __restrict__ Wmask,
               const float* __restrict__ gen_b2,
               const float* __restrict__ col_w,
               const float* __restrict__ col_b,
               float* __restrict__ xmean) {
    extern __shared__ char smc[];
    __half* Zms  = (__half*)(smc + SO_ZM);
    __half* G1s  = (__half*)(smc + SO_G1);
    float*  outs = (float*)(smc + SO_OUT);

    const int tid  = threadIdx.x;
    const int lane = tid & 31;
    const int warp = tid >> 5;
    const int r0   = (warp & 3) * 32;      // m-stripe
    const int ng   = warp >> 2;            // n-group 0..4
    const int j    = blockIdx.y;
    const int b0   = blockIdx.x * MT;
    const int seg  = lane >> 3, rr = lane & 7;

    const uint32_t zms_a  = (uint32_t)__cvta_generic_to_shared(smc + SO_ZM);
    const uint32_t g1s_a  = (uint32_t)__cvta_generic_to_shared(smc + SO_G1);
    const uint32_t w1s_a  = (uint32_t)__cvta_generic_to_shared(smc + SO_W1);
    const uint32_t ring_a = (uint32_t)__cvta_generic_to_shared(smc + SO_RING);

    // ---- prologue cp.async: W1, chunks 0,1,2 (4 groups)
    {
        const __half* w1 = g_w1h;
        for (int u = tid; u < W1_U; u += NTHR)
            cp16(w1s_a + u * 16, w1 + u * 8);
        cp_commit();
        #pragma unroll
        for (int c = 0; c < 3; c++) {
            const __half* src = g_w2h + c * CHUNK_H;
            for (int u = tid; u < CHUNK_U; u += NTHR)
                cp16(ring_a + c * CHUNK_B + u * 16, src + u * 8);
            cp_commit();
        }
    }

    // ---- stage masked z as fp16
    for (int idx = tid; idx < MT * LL; idx += NTHR) {
        int bl = idx >> 5, l = idx & 31;
        float v = g_z[(b0 + bl) * LL + l] * __ldg(Wmask + j * LL + l);
        Zms[bl * ZS + l] = __float2half(v);
    }
    if (tid < MT) outs[tid] = 0.f;

    asm volatile("cp.async.wait_group 3;");                 // W1 ready
    __syncthreads();

    // ldmatrix lane address components
    const int a_ro = (seg & 1) * 8 + rr;   // row offset within m16 tile
    const int a_cb = (seg >> 1) * 8;       // col base within k16
    const int b_k  = (seg & 1) * 8 + rr;   // k within chunk
    const int b_nb = (seg >> 1) * 8;       // n offset within n16 pair

    float acc[2][8][4];
    #pragma unroll
    for (int m = 0; m < 2; m++)
        #pragma unroll
        for (int t = 0; t < 8; t++)
            #pragma unroll
            for (int i = 0; i < 4; i++) acc[m][t][i] = 0.f;

    // ---- gemm1: G1 = relu(Zm @ W1), K=32 (2 k16 steps)
    #pragma unroll
    for (int kk = 0; kk < 2; kk++) {
        uint32_t a[2][4];
        #pragma unroll
        for (int m = 0; m < 2; m++)
            ldsm_x4(a[m], zms_a + ((r0 + m * 16 + a_ro) * ZS + kk * 16 + a_cb) * 2);
        #pragma unroll
        for (int p = 0; p < 4; p++) {
            int n0 = (ng * 8 + 2 * p) * 8;
            uint32_t b[4];
            ldsm_x4t(b, w1s_a + ((kk * 16 + b_k) * RS + n0 + b_nb) * 2);
            #pragma unroll
            for (int m = 0; m < 2; m++) {
                mma16(acc[m][2 * p],     a[m], b[0], b[1]);
                mma16(acc[m][2 * p + 1], a[m], b[2], b[3]);
            }
        }
    }
    {   // relu + pack -> G1s
        #pragma unroll
        for (int m = 0; m < 2; m++) {
            int row = r0 + m * 16 + (lane >> 2);
            #pragma unroll
            for (int t = 0; t < 8; t++) {
                int c = (ng * 8 + t) * 8 + 2 * (lane & 3);
                __half2 lo = __floats2half2_rn(fmaxf(acc[m][t][0], 0.f), fmaxf(acc[m][t][1], 0.f));
                __half2 hi = __floats2half2_rn(fmaxf(acc[m][t][2], 0.f), fmaxf(acc[m][t][3], 0.f));
                *(__half2*)(G1s + row * RS + c)       = lo;
                *(__half2*)(G1s + (row + 8) * RS + c) = hi;
                acc[m][t][0] = acc[m][t][1] = acc[m][t][2] = acc[m][t][3] = 0.f;
            }
        }
    }
    __syncthreads();    // G1s visible

    // ---- gemm2 mainloop: 19 chunks, 5-stage ring, prefetch distance 3
    for (int kc = 0; kc < KT; kc++) {
        // prefetch chunk kc+3 into stage (kc+3)%5 (its last reader, chunk
        // kc-2, finished before the barrier of iteration kc-1)
        if (kc + 3 < KT) {
            const __half* src = g_w2h + (kc + 3) * CHUNK_H;
            uint32_t dst = ring_a + ((kc + 3) % 5) * CHUNK_B;
            for (int u = tid; u < CHUNK_U; u += NTHR)
                cp16(dst + u * 16, src + u * 8);
        }
        cp_commit();    // one group per iteration (possibly empty)

        asm volatile("cp.async.wait_group 3;");   // chunk kc landed
        __syncthreads();

        const uint32_t Bs = ring_a + (kc % 5) * CHUNK_B;
        uint32_t a[2][4];
        #pragma unroll
        for (int m = 0; m < 2; m++)
            ldsm_x4(a[m], g1s_a + ((r0 + m * 16 + a_ro) * RS + kc * 16 + a_cb) * 2);
        #pragma unroll
        for (int p = 0; p < 4; p++) {
            int n0 = (ng * 8 + 2 * p) * 8;
            uint32_t b[4];
            ldsm_x4t(b, Bs + (b_k * RS + n0 + b_nb) * 2);
            #pragma unroll
            for (int m = 0; m < 2; m++) {
                mma16(acc[m][2 * p],     a[m], b[0], b[1]);
                mma16(acc[m][2 * p + 1], a[m], b[2], b[3]);
            }
        }
    }

    // ---- epilogue: relu(D2 + b2) . col_w[j], reduce
    #pragma unroll
    for (int m = 0; m < 2; m++) {
        float rs0 = 0.f, rs1 = 0.f;
        #pragma unroll
        for (int t = 0; t < 8; t++) {
            int cb = (ng * 8 + t) * 8 + 2 * (lane & 3);
            #pragma unroll
            for (int q = 0; q < 2; q++) {
                int c = cb + q;
                if (c < HH) {
                    float bb = __ldg(gen_b2 + c);
                    float cw = __ldg(col_w + j * HH + c);
                    rs0 += fmaxf(acc[m][t][q] + bb, 0.f) * cw;
                    rs1 += fmaxf(acc[m][t][2 + q] + bb, 0.f) * cw;
                }
            }
        }
        rs0 += __shfl_xor_sync(0xffffffffu, rs0, 1);
        rs0 += __shfl_xor_sync(0xffffffffu, rs0, 2);
        rs1 += __shfl_xor_sync(0xffffffffu, rs1, 1);
        rs1 += __shfl_xor_sync(0xffffffffu, rs1, 2);
        if ((lane & 3) == 0) {
            int rbase = r0 + m * 16 + (lane >> 2);
            atomicAdd(&outs[rbase], rs0);
            atomicAdd(&outs[rbase + 8], rs1);
        }
    }
    __syncthreads();
    if (tid < MT) {
        xmean[(b0 + tid) * DD + j] = outs[tid] + __ldg(col_b + j);
    }
}

// ---------------------------------------------------------------------------
// Launch
// ---------------------------------------------------------------------------
extern "C" void kernel_launch(void* const* d_in, const int* in_sizes, int n_in,
                              void* d_out, int out_size) {
    const float* x      = (const float*)d_in[0];
    const float* eps    = (const float*)d_in[1];
    const float* Wmask  = (const float*)d_in[2];
    const float* qz_w1  = (const float*)d_in[3];
    const float* qz_b1  = (const float*)d_in[4];
    const float* qz_w2  = (const float*)d_in[5];
    const float* qz_b2  = (const float*)d_in[6];
    const float* zm_w   = (const float*)d_in[7];
    const float* zm_b   = (const float*)d_in[8];
    const float* zl_w   = (const float*)d_in[9];
    const float* zl_b   = (const float*)d_in[10];
    const float* gen_w1 = (const float*)d_in[11];
    const float* gen_w2 = (const float*)d_in[12];
    const float* gen_b2 = (const float*)d_in[13];
    const float* col_w  = (const float*)d_in[14];
    const float* col_b  = (const float*)d_in[15];

    float* out    = (float*)d_out;
    float* xmean  = out;                       // [B, D]
    float* z_out  = out + BB * DD;             // [B, L]
    float* zm_out = z_out + BB * LL;
    float* zl_out = zm_out + BB * LL;

    float *h1_ptr = nullptr, *h2_ptr = nullptr;
    cudaGetSymbolAddress((void**)&h1_ptr, g_h1);
    cudaGetSymbolAddress((void**)&h2_ptr, g_h2);

    // Pack weights to fp16
    {
        int total = LL * RS + KT * CHUNK_H;
        pack_weights<<<(total + 255) / 256, 256>>>(gen_w1, gen_w2);
    }
    // Encoder
    {
        dim3 grid((HH + 63) / 64, (BB + 63) / 64);
        gemm_bias_relu<<<grid, 256>>>(x, qz_w1, qz_b1, h1_ptr, BB, HH, DD);
        gemm_bias_relu<<<grid, 256>>>(h1_ptr, qz_w2, qz_b2, h2_ptr, BB, HH, HH);
    }
    // Heads (split-K, 256 blocks)
    heads_kernel<<<BB / 2, 256>>>(zm_w, zm_b, zl_w, zl_b, eps,
                                  z_out, zm_out, zl_out);
    // fp16 mma.sync decoder
    {
        cudaFuncSetAttribute(decoder_kernel,
                             cudaFuncAttributeMaxDynamicSharedMemorySize,
                             SMEM_TOTAL);
        dim3 grid(BB / MT, DD);
        decoder_kernel<<<grid, NTHR, SMEM_TOTAL>>>(Wmask, gen_b2, col_w, col_b,
                                                   xmean);
    }
}

// round 8
// speedup vs baseline: 1.0601x; 1.0601x over previous
#include <cuda_runtime.h>
#include <cuda_fp16.h>
#include <cuda_bf16.h>
#include <math.h>
#include <stdint.h>

// Problem constants
#define BB 512   // batch
#define DD 512   // input dim / columns
#define LL 32    // latent
#define HH 300   // hidden
#define MT 128   // batch tile (M) in decoder
#define NP 320   // padded N (40 tiles of 8)
#define RS 328   // padded row stride (halves)
#define ZS 40    // Zms stride in halves
#define KCH 20   // k16-chunks in gemm2 (padded; chunk 19 is zeros)
#define NPAIR 10 // pair iterations
#define CHUNK_H (16 * RS)          // halves per W2 chunk = 5248
#define CHUNK_B (CHUNK_H * 2)      // bytes per chunk = 10496
#define CHUNK_U (CHUNK_B / 16)     // 16B units per chunk = 656
#define PAIR_B  (2 * CHUNK_B)      // bytes per chunk-pair = 20992
#define W1_U    (2 * CHUNK_U)      // W1 = 32 x RS = 1312 units

// SMEM layout (bytes)
#define SO_ZM   0                          // 10240
#define SO_G1   10240                      // 83968
#define SO_W1   94208                      // 20992
#define SO_RING 115200                     // 4 * 20992 = 83968
#define SO_B2   199168                     // 1280
#define SO_CW   200448                     // 1280
#define SO_OUT  201728                     // 512
#define SMEM_TOTAL 202240

// ---------------------------------------------------------------------------
// Scratch (device globals: allocation-free rule)
// ---------------------------------------------------------------------------
__device__ float g_h1[BB * HH];
__device__ float g_h2[BB * HH];
__device__ float g_z[BB * LL];
__device__ __half g_w1h[LL * RS];            // [32][328] fp16, padded
__device__ __half g_w2h[KCH * CHUNK_H];      // [20][16][328] fp16, chunk-contig

// ---------------------------------------------------------------------------
// PTX helpers
// ---------------------------------------------------------------------------
__device__ __forceinline__ void ldsm_x4(uint32_t* r, uint32_t addr) {
    asm volatile("ldmatrix.sync.aligned.m8n8.x4.shared.b16 {%0,%1,%2,%3}, [%4];"
                 : "=r"(r[0]), "=r"(r[1]), "=r"(r[2]), "=r"(r[3]) : "r"(addr));
}
__device__ __forceinline__ void ldsm_x4t(uint32_t* r, uint32_t addr) {
    asm volatile("ldmatrix.sync.aligned.m8n8.x4.trans.shared.b16 {%0,%1,%2,%3}, [%4];"
                 : "=r"(r[0]), "=r"(r[1]), "=r"(r[2]), "=r"(r[3]) : "r"(addr));
}
__device__ __forceinline__ void mma16(float* d, const uint32_t* a, uint32_t b0, uint32_t b1) {
    asm volatile(
        "mma.sync.aligned.m16n8k16.row.col.f32.f16.f16.f32 "
        "{%0,%1,%2,%3}, {%4,%5,%6,%7}, {%8,%9}, {%0,%1,%2,%3};"
        : "+f"(d[0]), "+f"(d[1]), "+f"(d[2]), "+f"(d[3])
        : "r"(a[0]), "r"(a[1]), "r"(a[2]), "r"(a[3]), "r"(b0), "r"(b1));
}
__device__ __forceinline__ void cp16(uint32_t dst, const void* src) {
    asm volatile("cp.async.cg.shared.global [%0], [%1], 16;" :: "r"(dst), "l"(src));
}
__device__ __forceinline__ void cp_commit() {
    asm volatile("cp.async.commit_group;");
}

// ---------------------------------------------------------------------------
// Pack weights to fp16 padded layouts (chunk 19 of W2 is all zeros)
// ---------------------------------------------------------------------------
__global__ void pack_weights(const float* __restrict__ gen_w1,
                             const float* __restrict__ gen_w2) {
    int idx = blockIdx.x * blockDim.x + threadIdx.x;
    if (idx < LL * RS) {
        int r = idx / RS, c = idx % RS;
        g_w1h[idx] = (c < HH) ? __float2half(gen_w1[r * HH + c]) : __half(0.f);
    } else {
        int i2 = idx - LL * RS;
        if (i2 < KCH * CHUNK_H) {
            int k = i2 / RS, c = i2 % RS;
            g_w2h[i2] = (k < HH && c < HH) ? __float2half(gen_w2[k * HH + c])
                                           : __half(0.f);
        }
    }
}

// ---------------------------------------------------------------------------
// Encoder SGEMM with bias + relu
// ---------------------------------------------------------------------------
__global__ void gemm_bias_relu(const float* __restrict__ A,
                               const float* __restrict__ Bw,
                               const float* __restrict__ bias,
                               float* __restrict__ C,
                               int M, int N, int K) {
    const int BK = 8;
    __shared__ float As[BK][64];
    __shared__ float Bs[BK][64];
    int tid = threadIdx.x;
    int tx = tid % 16, ty = tid / 16;
    int rowBase = blockIdx.y * 64;
    int colBase = blockIdx.x * 64;
    float acc[4][4] = {};
    for (int k0 = 0; k0 < K; k0 += BK) {
        #pragma unroll
        for (int i = 0; i < 2; i++) {
            int idx = tid * 2 + i;
            int r = idx / BK, kk = idx % BK;
            int gr = rowBase + r, gk = k0 + kk;
            As[kk][r] = (gr < M && gk < K) ? A[gr * K + gk] : 0.f;
        }
        #pragma unroll
        for (int i = 0; i < 2; i++) {
            int idx = tid * 2 + i;
            int kk = idx / 64, c = idx % 64;
            int gc = colBase + c, gk = k0 + kk;
            Bs[kk][c] = (gc < N && gk < K) ? Bw[gk * N + gc] : 0.f;
        }
        __syncthreads();
        #pragma unroll
        for (int kk = 0; kk < BK; kk++) {
            float a[4], b[4];
            #pragma unroll
            for (int i = 0; i < 4; i++) a[i] = As[kk][ty * 4 + i];
            #pragma unroll
            for (int jj = 0; jj < 4; jj++) b[jj] = Bs[kk][tx * 4 + jj];
            #pragma unroll
            for (int i = 0; i < 4; i++)
                #pragma unroll
                for (int jj = 0; jj < 4; jj++)
                    acc[i][jj] += a[i] * b[jj];
        }
        __syncthreads();
    }
    #pragma unroll
    for (int i = 0; i < 4; i++) {
        int r = rowBase + ty * 4 + i;
        if (r >= M) continue;
        #pragma unroll
        for (int jj = 0; jj < 4; jj++) {
            int c = colBase + tx * 4 + jj;
            if (c >= N) continue;
            float v = acc[i][jj] + bias[c];
            C[r * N + c] = v > 0.f ? v : 0.f;
        }
    }
}

// ---------------------------------------------------------------------------
// Heads, split-K: warp (b_loc, q) partials over h in [75q, 75q+75).
// ---------------------------------------------------------------------------
__global__ void heads_kernel(const float* __restrict__ zm_w,
                             const float* __restrict__ zm_b,
                             const float* __restrict__ zl_w,
                             const float* __restrict__ zl_b,
                             const float* __restrict__ eps,
                             float* __restrict__ z_out,
                             float* __restrict__ zm_out,
                             float* __restrict__ zl_out) {
    __shared__ float pam[8][32], pal[8][32];
    int lane = threadIdx.x & 31;
    int w = threadIdx.x >> 5;
    int b = blockIdx.x * 2 + (w >> 2);
    int q = w & 3;
    const float* h2row = g_h2 + b * HH;
    int h0 = q * 75;
    float am0 = 0.f, am1 = 0.f, am2 = 0.f;
    float al0 = 0.f, al1 = 0.f, al2 = 0.f;
    #pragma unroll 5
    for (int h = h0; h < h0 + 75; h += 3) {
        float v0 = __ldg(h2row + h);
        float v1 = __ldg(h2row + h + 1);
        float v2 = __ldg(h2row + h + 2);
        am0 += v0 * __ldg(zm_w + (h    ) * LL + lane);
        am1 += v1 * __ldg(zm_w + (h + 1) * LL + lane);
        am2 += v2 * __ldg(zm_w + (h + 2) * LL + lane);
        al0 += v0 * __ldg(zl_w + (h    ) * LL + lane);
        al1 += v1 * __ldg(zl_w + (h + 1) * LL + lane);
        al2 += v2 * __ldg(zl_w + (h + 2) * LL + lane);
    }
    pam[w][lane] = am0 + am1 + am2;
    pal[w][lane] = al0 + al1 + al2;
    __syncthreads();
    if (q == 0) {
        float am = pam[w][lane] + pam[w + 1][lane] + pam[w + 2][lane]
                 + pam[w + 3][lane] + zm_b[lane];
        float al = pal[w][lane] + pal[w + 1][lane] + pal[w + 2][lane]
                 + pal[w + 3][lane] + zl_b[lane];
        int o = b * LL + lane;
        float zv = am + eps[o] * expf(0.5f * al);
        zm_out[o] = am;
        zl_out[o] = al;
        z_out[o]  = zv;
        g_z[o]    = zv;
    }
}

// ---------------------------------------------------------------------------
// fp16 mma.sync fused decoder. CTA = (column j, 128-batch tile).
// 512 threads = 16 warps: warp & 3 -> m 32-row stripe (2 m16 tiles),
//                         warp >> 2 -> n-quarter (10 n8-tiles).
// Pair-wise mainloop: 10 iterations, 2 chunks each, 4 pair-slot ring.
// ---------------------------------------------------------------------------
__global__ void __launch_bounds__(512, 1)
decoder_kernel(const float* __restrict__ Wmask,
               const float* __restrict__ gen_b2,
               const float* __restrict__ col_w,
               const float* __restrict__ col_b,
               float* __restrict__ xmean) {
    extern __shared__ char smc[];
    __half* Zms  = (__half*)(smc + SO_ZM);
    __half* G1s  = (__half*)(smc + SO_G1);
    float*  b2s  = (float*)(smc + SO_B2);
    float*  cws  = (float*)(smc + SO_CW);
    float*  outs = (float*)(smc + SO_OUT);

    const int tid  = threadIdx.x;
    const int lane = tid & 31;
    const int warp = tid >> 5;
    const int r0   = (warp & 3) * 32;      // m-stripe (2 m16 tiles)
    const int nq   = warp >> 2;            // n-quarter (0..3)
    const int j    = blockIdx.y;
    const int b0   = blockIdx.x * MT;
    const int seg  = lane >> 3, rr = lane & 7;

    const uint32_t zms_a  = (uint32_t)__cvta_generic_to_shared(smc + SO_ZM);
    const uint32_t g1s_a  = (uint32_t)__cvta_generic_to_shared(smc + SO_G1);
    const uint32_t w1s_a  = (uint32_t)__cvta_generic_to_shared(smc + SO_W1);
    const uint32_t ring_a = (uint32_t)__cvta_generic_to_shared(smc + SO_RING);

    // ---- prologue cp.async: W1 (group), pair0 (group), pair1 (group)
    {
        const __half* w1 = g_w1h;
        for (int u = tid; u < W1_U; u += 512)
            cp16(w1s_a + u * 16, w1 + u * 8);
        cp_commit();
        #pragma unroll
        for (int p = 0; p < 2; p++) {
            const __half* src = g_w2h + p * 2 * CHUNK_H;
            for (int u = tid; u < 2 * CHUNK_U; u += 512)
                cp16(ring_a + p * PAIR_B + u * 16, src + u * 8);
            cp_commit();
        }
    }

    // ---- stage masked z as fp16; stage b2/col_w; init outs
    for (int idx = tid; idx < MT * LL; idx += 512) {
        int bl = idx >> 5, l = idx & 31;
        float v = g_z[(b0 + bl) * LL + l] * __ldg(Wmask + j * LL + l);
        Zms[bl * ZS + l] = __float2half(v);
    }
    for (int c = tid; c < NP; c += 512) {
        b2s[c] = (c < HH) ? __ldg(gen_b2 + c) : 0.f;
        cws[c] = (c < HH) ? __ldg(col_w + j * HH + c) : 0.f;
    }
    if (tid < MT) outs[tid] = 0.f;

    asm volatile("cp.async.wait_group 2;");   // W1 landed
    __syncthreads();

    // ldmatrix lane address components
    const int a_ro = (seg & 1) * 8 + rr;   // row offset within m16 tile
    const int a_cb = (seg >> 1) * 8;       // col base within k16
    const int b_k  = (seg & 1) * 8 + rr;   // k within chunk
    const int b_nb = (seg >> 1) * 8;       // n offset within n16 pair

    float acc[2][10][4];
    #pragma unroll
    for (int m = 0; m < 2; m++)
        #pragma unroll
        for (int t = 0; t < 10; t++)
            #pragma unroll
            for (int i = 0; i < 4; i++) acc[m][t][i] = 0.f;

    // ---- gemm1: G1 = relu(Zm @ W1), K=32 (2 k16 steps)
    #pragma unroll
    for (int kk = 0; kk < 2; kk++) {
        uint32_t a[2][4];
        #pragma unroll
        for (int m = 0; m < 2; m++)
            ldsm_x4(a[m], zms_a + ((r0 + m * 16 + a_ro) * ZS + kk * 16 + a_cb) * 2);
        #pragma unroll
        for (int p = 0; p < 5; p++) {
            int n0 = (nq * 10 + 2 * p) * 8;
            uint32_t b[4];
            ldsm_x4t(b, w1s_a + ((kk * 16 + b_k) * RS + n0 + b_nb) * 2);
            #pragma unroll
            for (int m = 0; m < 2; m++) {
                mma16(acc[m][2 * p],     a[m], b[0], b[1]);
                mma16(acc[m][2 * p + 1], a[m], b[2], b[3]);
            }
        }
    }
    {   // relu + pack -> G1s
        #pragma unroll
        for (int m = 0; m < 2; m++) {
            int row = r0 + m * 16 + (lane >> 2);
            #pragma unroll
            for (int t = 0; t < 10; t++) {
                int c = (nq * 10 + t) * 8 + 2 * (lane & 3);
                __half2 lo = __floats2half2_rn(fmaxf(acc[m][t][0], 0.f), fmaxf(acc[m][t][1], 0.f));
                __half2 hi = __floats2half2_rn(fmaxf(acc[m][t][2], 0.f), fmaxf(acc[m][t][3], 0.f));
                *(__half2*)(G1s + row * RS + c)       = lo;
                *(__half2*)(G1s + (row + 8) * RS + c) = hi;
                acc[m][t][0] = acc[m][t][1] = acc[m][t][2] = acc[m][t][3] = 0.f;
            }
        }
    }
    __syncthreads();    // G1s visible

    // ---- gemm2 mainloop: 10 pair-iterations, 4 pair-slot ring, prefetch dist 2
    for (int ip = 0; ip < NPAIR; ip++) {
        if (ip + 2 < NPAIR) {
            const __half* src = g_w2h + (ip + 2) * 2 * CHUNK_H;
            uint32_t dst = ring_a + ((ip + 2) & 3) * PAIR_B;
            for (int u = tid; u < 2 * CHUNK_U; u += 512)
                cp16(dst + u * 16, src + u * 8);
        }
        cp_commit();    // one group per iteration (possibly empty)

        asm volatile("cp.async.wait_group 2;");   // pair ip landed
        __syncthreads();

        const uint32_t pbase = ring_a + (ip & 3) * PAIR_B;
        #pragma unroll
        for (int q = 0; q < 2; q++) {
            const int kc = 2 * ip + q;
            const uint32_t Bs = pbase + q * CHUNK_B;
            uint32_t a[2][4];
            #pragma unroll
            for (int m = 0; m < 2; m++)
                ldsm_x4(a[m], g1s_a + ((r0 + m * 16 + a_ro) * RS + kc * 16 + a_cb) * 2);
            #pragma unroll
            for (int p = 0; p < 5; p++) {
                int n0 = (nq * 10 + 2 * p) * 8;
                uint32_t b[4];
                ldsm_x4t(b, Bs + (b_k * RS + n0 + b_nb) * 2);
                #pragma unroll
                for (int m = 0; m < 2; m++) {
                    mma16(acc[m][2 * p],     a[m], b[0], b[1]);
                    mma16(acc[m][2 * p + 1], a[m], b[2], b[3]);
                }
            }
        }
    }

    // ---- epilogue: relu(D2 + b2) . col_w[j], reduce (padded cols: cw=0)
    #pragma unroll
    for (int m = 0; m < 2; m++) {
        float rs0 = 0.f, rs1 = 0.f;
        #pragma unroll
        for (int t = 0; t < 10; t++) {
            int cb = (nq * 10 + t) * 8 + 2 * (lane & 3);
            #pragma unroll
            for (int q = 0; q < 2; q++) {
                int c = cb + q;
                float bb = b2s[c];
                float cw = cws[c];
                rs0 += fmaxf(acc[m][t][q] + bb, 0.f) * cw;
                rs1 += fmaxf(acc[m][t][2 + q] + bb, 0.f) * cw;
            }
        }
        rs0 += __shfl_xor_sync(0xffffffffu, rs0, 1);
        rs0 += __shfl_xor_sync(0xffffffffu, rs0, 2);
        rs1 += __shfl_xor_sync(0xffffffffu, rs1, 1);
        rs1 += __shfl_xor_sync(0xffffffffu, rs1, 2);
        if ((lane & 3) == 0) {
            int rbase = r0 + m * 16 + (lane >> 2);
            atomicAdd(&outs[rbase], rs0);
            atomicAdd(&outs[rbase + 8], rs1);
        }
    }
    __syncthreads();
    if (tid < MT) {
        xmean[(b0 + tid) * DD + j] = outs[tid] + __ldg(col_b + j);
    }
}

// ---------------------------------------------------------------------------
// Launch
// ---------------------------------------------------------------------------
extern "C" void kernel_launch(void* const* d_in, const int* in_sizes, int n_in,
                              void* d_out, int out_size) {
    const float* x      = (const float*)d_in[0];
    const float* eps    = (const float*)d_in[1];
    const float* Wmask  = (const float*)d_in[2];
    const float* qz_w1  = (const float*)d_in[3];
    const float* qz_b1  = (const float*)d_in[4];
    const float* qz_w2  = (const float*)d_in[5];
    const float* qz_b2  = (const float*)d_in[6];
    const float* zm_w   = (const float*)d_in[7];
    const float* zm_b   = (const float*)d_in[8];
    const float* zl_w   = (const float*)d_in[9];
    const float* zl_b   = (const float*)d_in[10];
    const float* gen_w1 = (const float*)d_in[11];
    const float* gen_w2 = (const float*)d_in[12];
    const float* gen_b2 = (const float*)d_in[13];
    const float* col_w  = (const float*)d_in[14];
    const float* col_b  = (const float*)d_in[15];

    float* out    = (float*)d_out;
    float* xmean  = out;                       // [B, D]
    float* z_out  = out + BB * DD;             // [B, L]
    float* zm_out = z_out + BB * LL;
    float* zl_out = zm_out + BB * LL;

    float *h1_ptr = nullptr, *h2_ptr = nullptr;
    cudaGetSymbolAddress((void**)&h1_ptr, g_h1);
    cudaGetSymbolAddress((void**)&h2_ptr, g_h2);

    // Pack weights to fp16
    {
        int total = LL * RS + KCH * CHUNK_H;
        pack_weights<<<(total + 255) / 256, 256>>>(gen_w1, gen_w2);
    }
    // Encoder
    {
        dim3 grid((HH + 63) / 64, (BB + 63) / 64);
        gemm_bias_relu<<<grid, 256>>>(x, qz_w1, qz_b1, h1_ptr, BB, HH, DD);
        gemm_bias_relu<<<grid, 256>>>(h1_ptr, qz_w2, qz_b2, h2_ptr, BB, HH, HH);
    }
    // Heads (split-K, 256 blocks)
    heads_kernel<<<BB / 2, 256>>>(zm_w, zm_b, zl_w, zl_b, eps,
                                  z_out, zm_out, zl_out);
    // fp16 mma.sync decoder
    {
        cudaFuncSetAttribute(decoder_kernel,
                             cudaFuncAttributeMaxDynamicSharedMemorySize,
                             SMEM_TOTAL);
        dim3 grid(BB / MT, DD);
        decoder_kernel<<<grid, 512, SMEM_TOTAL>>>(Wmask, gen_b2, col_w, col_b,
                                                  xmean);
    }
}

// round 10
// speedup vs baseline: 1.3088x; 1.2346x over previous
#include <cuda_runtime.h>
#include <cuda_fp16.h>
#include <cuda_bf16.h>
#include <math.h>
#include <stdint.h>

// Problem constants
#define BB 512   // batch
#define DD 512   // input dim / columns
#define LL 32    // latent
#define HH 300   // hidden
#define MT 128   // batch tile (M) in decoder
#define NP 320   // padded N (40 tiles of 8)
#define RS 328   // padded row stride (halves)
#define ZS 40    // Zms stride in halves
#define KCH 20   // k16-chunks in gemm2 (padded; chunk 19 is zeros)
#define NPAIR 10 // pair iterations (decoder / enc2)
#define CHUNK_H (16 * RS)          // halves per chunk = 5248
#define CHUNK_B (CHUNK_H * 2)      // bytes per chunk = 10496
#define CHUNK_U (CHUNK_B / 16)     // 16B units per chunk = 656
#define PAIR_B  (2 * CHUNK_B)      // bytes per chunk-pair = 20992
#define W1_U    (2 * CHUNK_U)      // W1 = 32 x RS = 1312 units

// Decoder SMEM layout (bytes)
#define SO_ZM   0                          // 10240
#define SO_G1   10240                      // 83968
#define SO_W1   94208                      // 20992
#define SO_RING 115200                     // 4 * 20992 = 83968
#define SO_B2   199168                     // 1280
#define SO_CW   200448                     // 1280
#define SO_OUT  201728                     // 512
#define SMEM_TOTAL 202240

// enc1 SMEM layout
#define E1_XS   0                          // 64*520*2 = 66560
#define E1_RING 66560                      // 4*PAIR_B = 83968
#define E1_B1   150528                     // 1280
#define E1_SMEM 151808

// enc2 SMEM layout
#define E2_H1   0                          // 64*328*2 = 41984
#define E2_H2   41984                      // 41984
#define E2_RING 83968                      // 4*PAIR_B = 83968
#define E2_ZW   167936                     // 320*72*2 = 46080
#define E2_B2   214016                     // 1280
#define E2_ZB   215296                     // 2*64*4 = 512
#define E2_SMEM 215808
#define ZWS 72   // zm|zl weight stride (halves)

// ---------------------------------------------------------------------------
// Scratch (device globals: allocation-free rule)
// ---------------------------------------------------------------------------
__device__ float  g_z[BB * LL];
__device__ __half g_w1h[LL * RS];            // decoder W1 [32][328]
__device__ __half g_w2h[KCH * CHUNK_H];      // decoder W2 [20][16][328]
__device__ __half g_ew1[32 * CHUNK_H];       // qz_w1 [32 chunks][16][328]
__device__ __half g_ew2[KCH * CHUNK_H];      // qz_w2 [20 chunks][16][328]
__device__ __half g_zw[NP * ZWS];            // zm|zl [320 k][72]
__device__ __half g_h1h[BB * RS];            // h1 fp16 [512][328]

// ---------------------------------------------------------------------------
// PTX helpers
// ---------------------------------------------------------------------------
__device__ __forceinline__ void ldsm_x4(uint32_t* r, uint32_t addr) {
    asm volatile("ldmatrix.sync.aligned.m8n8.x4.shared.b16 {%0,%1,%2,%3}, [%4];"
                 : "=r"(r[0]), "=r"(r[1]), "=r"(r[2]), "=r"(r[3]) : "r"(addr));
}
__device__ __forceinline__ void ldsm_x4t(uint32_t* r, uint32_t addr) {
    asm volatile("ldmatrix.sync.aligned.m8n8.x4.trans.shared.b16 {%0,%1,%2,%3}, [%4];"
                 : "=r"(r[0]), "=r"(r[1]), "=r"(r[2]), "=r"(r[3]) : "r"(addr));
}
__device__ __forceinline__ void mma16(float* d, const uint32_t* a, uint32_t b0, uint32_t b1) {
    asm volatile(
        "mma.sync.aligned.m16n8k16.row.col.f32.f16.f16.f32 "
        "{%0,%1,%2,%3}, {%4,%5,%6,%7}, {%8,%9}, {%0,%1,%2,%3};"
        : "+f"(d[0]), "+f"(d[1]), "+f"(d[2]), "+f"(d[3])
        : "r"(a[0]), "r"(a[1]), "r"(a[2]), "r"(a[3]), "r"(b0), "r"(b1));
}
__device__ __forceinline__ void cp16(uint32_t dst, const void* src) {
    asm volatile("cp.async.cg.shared.global [%0], [%1], 16;" :: "r"(dst), "l"(src));
}
__device__ __forceinline__ void cp_commit() {
    asm volatile("cp.async.commit_group;");
}

// ---------------------------------------------------------------------------
// Pack all fp16 weight images
// ---------------------------------------------------------------------------
__global__ void pack_weights(const float* __restrict__ gen_w1,
                             const float* __restrict__ gen_w2,
                             const float* __restrict__ qz_w1,
                             const float* __restrict__ qz_w2,
                             const float* __restrict__ zm_w,
                             const float* __restrict__ zl_w) {
    int idx = blockIdx.x * blockDim.x + threadIdx.x;
    const int S0 = LL * RS;                 // 10496
    const int S1 = S0 + KCH * CHUNK_H;      // +104960
    const int S2 = S1 + 32 * CHUNK_H;       // +167936
    const int S3 = S2 + KCH * CHUNK_H;      // +104960
    const int S4 = S3 + NP * ZWS;           // +23040
    if (idx < S0) {
        int r = idx / RS, c = idx % RS;
        g_w1h[idx] = (c < HH) ? __float2half(gen_w1[r * HH + c]) : __half(0.f);
    } else if (idx < S1) {
        int i = idx - S0;
        int k = i / RS, c = i % RS;
        g_w2h[i] = (k < HH && c < HH) ? __float2half(gen_w2[k * HH + c]) : __half(0.f);
    } else if (idx < S2) {
        int i = idx - S1;
        int k = i / RS, c = i % RS;         // k in 0..511
        g_ew1[i] = (c < HH) ? __float2half(qz_w1[k * HH + c]) : __half(0.f);
    } else if (idx < S3) {
        int i = idx - S2;
        int k = i / RS, c = i % RS;
        g_ew2[i] = (k < HH && c < HH) ? __float2half(qz_w2[k * HH + c]) : __half(0.f);
    } else if (idx < S4) {
        int i = idx - S3;
        int k = i / ZWS, c = i % ZWS;
        float v = 0.f;
        if (k < HH) {
            if (c < 32) v = zm_w[k * LL + c];
            else if (c < 64) v = zl_w[k * LL + (c - 32)];
        }
        g_zw[i] = __float2half(v);
    }
}

// ---------------------------------------------------------------------------
// enc1: h1 = relu(x @ qz_w1 + b1), fp16 mma. CTA = 64 batch rows. 512 thr.
// warps: warp&3 -> m16 stripe, warp>>2 -> n-quarter (10 n8-tiles).
// ---------------------------------------------------------------------------
__global__ void __launch_bounds__(512, 1)
enc1_kernel(const float* __restrict__ x, const float* __restrict__ qz_b1) {
    extern __shared__ char smc[];
    __half* xs  = (__half*)(smc + E1_XS);
    float*  b1s = (float*)(smc + E1_B1);
    const uint32_t xs_a   = (uint32_t)__cvta_generic_to_shared(smc + E1_XS);
    const uint32_t ring_a = (uint32_t)__cvta_generic_to_shared(smc + E1_RING);

    const int tid  = threadIdx.x;
    const int lane = tid & 31;
    const int warp = tid >> 5;
    const int ms   = (warp & 3) * 16;
    const int nq   = warp >> 2;
    const int m0   = blockIdx.x * 64;
    const int seg  = lane >> 3, rr = lane & 7;

    // prologue: pairs 0,1 of qz_w1
    #pragma unroll
    for (int p = 0; p < 2; p++) {
        const __half* src = g_ew1 + p * 2 * CHUNK_H;
        for (int u = tid; u < 2 * CHUNK_U; u += 512)
            cp16(ring_a + p * PAIR_B + u * 16, src + u * 8);
        cp_commit();
    }

    // stage x tile (64 x 512) as fp16, stride 520
    for (int i = tid; i < 64 * 256; i += 512) {
        int r = i >> 8, c2 = i & 255;
        float2 v = *(const float2*)(x + (m0 + r) * 512 + c2 * 2);
        *(__half2*)(xs + r * 520 + c2 * 2) = __floats2half2_rn(v.x, v.y);
    }
    for (int c = tid; c < NP; c += 512)
        b1s[c] = (c < HH) ? qz_b1[c] : 0.f;
    __syncthreads();

    const int a_ro = (seg & 1) * 8 + rr;
    const int a_cb = (seg >> 1) * 8;
    const int b_k  = (seg & 1) * 8 + rr;
    const int b_nb = (seg >> 1) * 8;

    float acc[10][4];
    #pragma unroll
    for (int t = 0; t < 10; t++)
        #pragma unroll
        for (int i = 0; i < 4; i++) acc[t][i] = 0.f;

    // mainloop: 16 pairs (k = 512)
    for (int ip = 0; ip < 16; ip++) {
        if (ip + 2 < 16) {
            const __half* src = g_ew1 + (ip + 2) * 2 * CHUNK_H;
            uint32_t dst = ring_a + ((ip + 2) & 3) * PAIR_B;
            for (int u = tid; u < 2 * CHUNK_U; u += 512)
                cp16(dst + u * 16, src + u * 8);
        }
        cp_commit();
        asm volatile("cp.async.wait_group 2;");
        __syncthreads();

        const uint32_t pbase = ring_a + (ip & 3) * PAIR_B;
        #pragma unroll
        for (int q = 0; q < 2; q++) {
            const int kc = 2 * ip + q;
            const uint32_t Bs = pbase + q * CHUNK_B;
            uint32_t a[4];
            ldsm_x4(a, xs_a + ((ms + a_ro) * 520 + kc * 16 + a_cb) * 2);
            #pragma unroll
            for (int p = 0; p < 5; p++) {
                int n0 = (nq * 10 + 2 * p) * 8;
                uint32_t b[4];
                ldsm_x4t(b, Bs + (b_k * RS + n0 + b_nb) * 2);
                mma16(acc[2 * p],     a, b[0], b[1]);
                mma16(acc[2 * p + 1], a, b[2], b[3]);
            }
        }
    }

    // epilogue: relu(acc + b1) -> g_h1h fp16
    {
        int row = ms + (lane >> 2);
        #pragma unroll
        for (int t = 0; t < 10; t++) {
            int c = (nq * 10 + t) * 8 + 2 * (lane & 3);
            float v0 = fmaxf(acc[t][0] + b1s[c], 0.f);
            float v1 = fmaxf(acc[t][1] + b1s[c + 1], 0.f);
            float v2 = fmaxf(acc[t][2] + b1s[c], 0.f);
            float v3 = fmaxf(acc[t][3] + b1s[c + 1], 0.f);
            *(__half2*)(g_h1h + (m0 + row) * RS + c)     = __floats2half2_rn(v0, v1);
            *(__half2*)(g_h1h + (m0 + row + 8) * RS + c) = __floats2half2_rn(v2, v3);
        }
    }
}

// ---------------------------------------------------------------------------
// enc2 + heads fused: h2 = relu(h1 @ qz_w2 + b2); zm/zl = h2 @ [zm_w|zl_w] + b;
// z = zm + eps*exp(0.5 zl). CTA = 64 batch rows. 512 threads.
// ---------------------------------------------------------------------------
__global__ void __launch_bounds__(512, 1)
enc2_heads_kernel(const float* __restrict__ eps,
                  const float* __restrict__ qz_b2,
                  const float* __restrict__ zm_b,
                  const float* __restrict__ zl_b,
                  float* __restrict__ z_out,
                  float* __restrict__ zm_out,
                  float* __restrict__ zl_out) {
    extern __shared__ char smc[];
    float* b2s = (float*)(smc + E2_B2);
    float* zbb = (float*)(smc + E2_ZB);      // [0..31] zm_b, [64..95] zl_b
    float* zbuf = (float*)(smc + E2_RING);   // alias ring: f32 [64][68]
    const uint32_t h1_a   = (uint32_t)__cvta_generic_to_shared(smc + E2_H1);
    const uint32_t h2_a   = (uint32_t)__cvta_generic_to_shared(smc + E2_H2);
    const uint32_t ring_a = (uint32_t)__cvta_generic_to_shared(smc + E2_RING);
    const uint32_t zw_a   = (uint32_t)__cvta_generic_to_shared(smc + E2_ZW);
    __half* h2s = (__half*)(smc + E2_H2);

    const int tid  = threadIdx.x;
    const int lane = tid & 31;
    const int warp = tid >> 5;
    const int ms   = (warp & 3) * 16;
    const int nq   = warp >> 2;
    const int m0   = blockIdx.x * 64;
    const int seg  = lane >> 3, rr = lane & 7;

    // prologue: h1 tile (group), zw (group), pairs 0,1 of qz_w2 (2 groups)
    {
        const __half* h1src = g_h1h + m0 * RS;
        for (int u = tid; u < 64 * RS / 8; u += 512)
            cp16(h1_a + u * 16, h1src + u * 8);
        cp_commit();
        for (int u = tid; u < NP * ZWS / 8; u += 512)
            cp16(zw_a + u * 16, g_zw + u * 8);
        cp_commit();
        #pragma unroll
        for (int p = 0; p < 2; p++) {
            const __half* src = g_ew2 + p * 2 * CHUNK_H;
            for (int u = tid; u < 2 * CHUNK_U; u += 512)
                cp16(ring_a + p * PAIR_B + u * 16, src + u * 8);
            cp_commit();
        }
    }
    for (int c = tid; c < NP; c += 512)
        b2s[c] = (c < HH) ? qz_b2[c] : 0.f;
    if (tid < 32) zbb[tid] = zm_b[tid];
    else if (tid < 64) zbb[64 + tid - 32] = zl_b[tid - 32];

    asm volatile("cp.async.wait_group 2;");  // h1 + zw landed
    __syncthreads();

    const int a_ro = (seg & 1) * 8 + rr;
    const int a_cb = (seg >> 1) * 8;
    const int b_k  = (seg & 1) * 8 + rr;
    const int b_nb = (seg >> 1) * 8;

    float acc[10][4];
    #pragma unroll
    for (int t = 0; t < 10; t++)
        #pragma unroll
        for (int i = 0; i < 4; i++) acc[t][i] = 0.f;

    // gemm2 mainloop: 10 pairs (k = 320; chunk 19 is zero -> skip)
    for (int ip = 0; ip < NPAIR; ip++) {
        if (ip + 2 < NPAIR) {
            const __half* src = g_ew2 + (ip + 2) * 2 * CHUNK_H;
            uint32_t dst = ring_a + ((ip + 2) & 3) * PAIR_B;
            for (int u = tid; u < 2 * CHUNK_U; u += 512)
                cp16(dst + u * 16, src + u * 8);
        }
        cp_commit();
        asm volatile("cp.async.wait_group 2;");
        __syncthreads();

        const uint32_t pbase = ring_a + (ip & 3) * PAIR_B;
        #pragma unroll
        for (int q = 0; q < 2; q++) {
            const int kc = 2 * ip + q;
            if (kc < 19) {
                const uint32_t Bs = pbase + q * CHUNK_B;
                uint32_t a[4];
                ldsm_x4(a, h1_a + ((ms + a_ro) * RS + kc * 16 + a_cb) * 2);
                #pragma unroll
                for (int p = 0; p < 5; p++) {
                    int n0 = (nq * 10 + 2 * p) * 8;
                    uint32_t b[4];
                    ldsm_x4t(b, Bs + (b_k * RS + n0 + b_nb) * 2);
                    mma16(acc[2 * p],     a, b[0], b[1]);
                    mma16(acc[2 * p + 1], a, b[2], b[3]);
                }
            }
        }
    }

    // h2 = relu(acc + b2) -> h2s (fp16, stride RS)
    {
        int row = ms + (lane >> 2);
        #pragma unroll
        for (int t = 0; t < 10; t++) {
            int c = (nq * 10 + t) * 8 + 2 * (lane & 3);
            float v0 = fmaxf(acc[t][0] + b2s[c], 0.f);
            float v1 = fmaxf(acc[t][1] + b2s[c + 1], 0.f);
            float v2 = fmaxf(acc[t][2] + b2s[c], 0.f);
            float v3 = fmaxf(acc[t][3] + b2s[c + 1], 0.f);
            *(__half2*)(h2s + row * RS + c)       = __floats2half2_rn(v0, v1);
            *(__half2*)(h2s + (row + 8) * RS + c) = __floats2half2_rn(v2, v3);
        }
    }
    __syncthreads();

    // heads gemm: [zm|zl] = h2 @ zw, k = 304 (19 steps), n = 64 (2 tiles/warp)
    float ah[2][4];
    #pragma unroll
    for (int t = 0; t < 2; t++)
        #pragma unroll
        for (int i = 0; i < 4; i++) ah[t][i] = 0.f;
    for (int ks = 0; ks < 19; ks++) {
        uint32_t a[4];
        ldsm_x4(a, h2_a + ((ms + a_ro) * RS + ks * 16 + a_cb) * 2);
        int n0 = nq * 16;
        uint32_t b[4];
        ldsm_x4t(b, zw_a + ((ks * 16 + b_k) * ZWS + n0 + b_nb) * 2);
        mma16(ah[0], a, b[0], b[1]);
        mma16(ah[1], a, b[2], b[3]);
    }
    __syncthreads();   // ring fully consumed; safe to alias zbuf

    // write zm|zl to zbuf f32 [64][68]
    {
        int row = ms + (lane >> 2);
        #pragma unroll
        for (int t = 0; t < 2; t++) {
            int c = nq * 16 + t * 8 + 2 * (lane & 3);
            zbuf[row * 68 + c]           = ah[t][0];
            zbuf[row * 68 + c + 1]       = ah[t][1];
            zbuf[(row + 8) * 68 + c]     = ah[t][2];
            zbuf[(row + 8) * 68 + c + 1] = ah[t][3];
        }
    }
    __syncthreads();

    // elementwise heads epilogue
    for (int i = tid; i < 64 * LL; i += 512) {
        int r = i >> 5, l = i & 31;
        float zm = zbuf[r * 68 + l] + zbb[l];
        float zl = zbuf[r * 68 + 32 + l] + zbb[64 + l];
        int o = (m0 + r) * LL + l;
        float zv = zm + eps[o] * expf(0.5f * zl);
        zm_out[o] = zm;
        zl_out[o] = zl;
        z_out[o]  = zv;
        g_z[o]    = zv;
    }
}

// ---------------------------------------------------------------------------
// fp16 mma.sync fused decoder (R8, + zero-chunk skip). CTA = (j, 128 rows).
// ---------------------------------------------------------------------------
__global__ void __launch_bounds__(512, 1)
decoder_kernel(const float* __restrict__ Wmask,
               const float* __restrict__ gen_b2,
               const float* __restrict__ col_w,
               const float* __restrict__ col_b,
               float* __restrict__ xmean) {
    extern __shared__ char smc[];
    __half* Zms  = (__half*)(smc + SO_ZM);
    __half* G1s  = (__half*)(smc + SO_G1);
    float*  b2s  = (float*)(smc + SO_B2);
    float*  cws  = (float*)(smc + SO_CW);
    float*  outs = (float*)(smc + SO_OUT);

    const int tid  = threadIdx.x;
    const int lane = tid & 31;
    const int warp = tid >> 5;
    const int r0   = (warp & 3) * 32;
    const int nq   = warp >> 2;
    const int j    = blockIdx.y;
    const int b0   = blockIdx.x * MT;
    const int seg  = lane >> 3, rr = lane & 7;

    const uint32_t zms_a  = (uint32_t)__cvta_generic_to_shared(smc + SO_ZM);
    const uint32_t g1s_a  = (uint32_t)__cvta_generic_to_shared(smc + SO_G1);
    const uint32_t w1s_a  = (uint32_t)__cvta_generic_to_shared(smc + SO_W1);
    const uint32_t ring_a = (uint32_t)__cvta_generic_to_shared(smc + SO_RING);

    {
        const __half* w1 = g_w1h;
        for (int u = tid; u < W1_U; u += 512)
            cp16(w1s_a + u * 16, w1 + u * 8);
        cp_commit();
        #pragma unroll
        for (int p = 0; p < 2; p++) {
            const __half* src = g_w2h + p * 2 * CHUNK_H;
            for (int u = tid; u < 2 * CHUNK_U; u += 512)
                cp16(ring_a + p * PAIR_B + u * 16, src + u * 8);
            cp_commit();
        }
    }

    for (int idx = tid; idx < MT * LL; idx += 512) {
        int bl = idx >> 5, l = idx & 31;
        float v = g_z[(b0 + bl) * LL + l] * __ldg(Wmask + j * LL + l);
        Zms[bl * ZS + l] = __float2half(v);
    }
    for (int c = tid; c < NP; c += 512) {
        b2s[c] = (c < HH) ? __ldg(gen_b2 + c) : 0.f;
        cws[c] = (c < HH) ? __ldg(col_w + j * HH + c) : 0.f;
    }
    if (tid < MT) outs[tid] = 0.f;

    asm volatile("cp.async.wait_group 2;");
    __syncthreads();

    const int a_ro = (seg & 1) * 8 + rr;
    const int a_cb = (seg >> 1) * 8;
    const int b_k  = (seg & 1) * 8 + rr;
    const int b_nb = (seg >> 1) * 8;

    float acc[2][10][4];
    #pragma unroll
    for (int m = 0; m < 2; m++)
        #pragma unroll
        for (int t = 0; t < 10; t++)
            #pragma unroll
            for (int i = 0; i < 4; i++) acc[m][t][i] = 0.f;

    #pragma unroll
    for (int kk = 0; kk < 2; kk++) {
        uint32_t a[2][4];
        #pragma unroll
        for (int m = 0; m < 2; m++)
            ldsm_x4(a[m], zms_a + ((r0 + m * 16 + a_ro) * ZS + kk * 16 + a_cb) * 2);
        #pragma unroll
        for (int p = 0; p < 5; p++) {
            int n0 = (nq * 10 + 2 * p) * 8;
            uint32_t b[4];
            ldsm_x4t(b, w1s_a + ((kk * 16 + b_k) * RS + n0 + b_nb) * 2);
            #pragma unroll
            for (int m = 0; m < 2; m++) {
                mma16(acc[m][2 * p],     a[m], b[0], b[1]);
                mma16(acc[m][2 * p + 1], a[m], b[2], b[3]);
            }
        }
    }
    {
        #pragma unroll
        for (int m = 0; m < 2; m++) {
            int row = r0 + m * 16 + (lane >> 2);
            #pragma unroll
            for (int t = 0; t < 10; t++) {
                int c = (nq * 10 + t) * 8 + 2 * (lane & 3);
                __half2 lo = __floats2half2_rn(fmaxf(acc[m][t][0], 0.f), fmaxf(acc[m][t][1], 0.f));
                __half2 hi = __floats2half2_rn(fmaxf(acc[m][t][2], 0.f), fmaxf(acc[m][t][3], 0.f));
                *(__half2*)(G1s + row * RS + c)       = lo;
                *(__half2*)(G1s + (row + 8) * RS + c) = hi;
                acc[m][t][0] = acc[m][t][1] = acc[m][t][2] = acc[m][t][3] = 0.f;
            }
        }
    }
    __syncthreads();

    for (int ip = 0; ip < NPAIR; ip++) {
        if (ip + 2 < NPAIR) {
            const __half* src = g_w2h + (ip + 2) * 2 * CHUNK_H;
            uint32_t dst = ring_a + ((ip + 2) & 3) * PAIR_B;
            for (int u = tid; u < 2 * CHUNK_U; u += 512)
                cp16(dst + u * 16, src + u * 8);
        }
        cp_commit();
        asm volatile("cp.async.wait_group 2;");
        __syncthreads();

        const uint32_t pbase = ring_a + (ip & 3) * PAIR_B;
        #pragma unroll
        for (int q = 0; q < 2; q++) {
            const int kc = 2 * ip + q;
            if (kc < 19) {
                const uint32_t Bs = pbase + q * CHUNK_B;
                uint32_t a[2][4];
                #pragma unroll
                for (int m = 0; m < 2; m++)
                    ldsm_x4(a[m], g1s_a + ((r0 + m * 16 + a_ro) * RS + kc * 16 + a_cb) * 2);
                #pragma unroll
                for (int p = 0; p < 5; p++) {
                    int n0 = (nq * 10 + 2 * p) * 8;
                    uint32_t b[4];
                    ldsm_x4t(b, Bs + (b_k * RS + n0 + b_nb) * 2);
                    #pragma unroll
                    for (int m = 0; m < 2; m++) {
                        mma16(acc[m][2 * p],     a[m], b[0], b[1]);
                        mma16(acc[m][2 * p + 1], a[m], b[2], b[3]);
                    }
                }
            }
        }
    }

    #pragma unroll
    for (int m = 0; m < 2; m++) {
        float rs0 = 0.f, rs1 = 0.f;
        #pragma unroll
        for (int t = 0; t < 10; t++) {
            int cb = (nq * 10 + t) * 8 + 2 * (lane & 3);
            #pragma unroll
            for (int q = 0; q < 2; q++) {
                int c = cb + q;
                float bb = b2s[c];
                float cw = cws[c];
                rs0 += fmaxf(acc[m][t][q] + bb, 0.f) * cw;
                rs1 += fmaxf(acc[m][t][2 + q] + bb, 0.f) * cw;
            }
        }
        rs0 += __shfl_xor_sync(0xffffffffu, rs0, 1);
        rs0 += __shfl_xor_sync(0xffffffffu, rs0, 2);
        rs1 += __shfl_xor_sync(0xffffffffu, rs1, 1);
        rs1 += __shfl_xor_sync(0xffffffffu, rs1, 2);
        if ((lane & 3) == 0) {
            int rbase = r0 + m * 16 + (lane >> 2);
            atomicAdd(&outs[rbase], rs0);
            atomicAdd(&outs[rbase + 8], rs1);
        }
    }
    __syncthreads();
    if (tid < MT) {
        xmean[(b0 + tid) * DD + j] = outs[tid] + __ldg(col_b + j);
    }
}

// ---------------------------------------------------------------------------
// Launch
// ---------------------------------------------------------------------------
extern "C" void kernel_launch(void* const* d_in, const int* in_sizes, int n_in,
                              void* d_out, int out_size) {
    const float* x      = (const float*)d_in[0];
    const float* eps    = (const float*)d_in[1];
    const float* Wmask  = (const float*)d_in[2];
    const float* qz_w1  = (const float*)d_in[3];
    const float* qz_b1  = (const float*)d_in[4];
    const float* qz_w2  = (const float*)d_in[5];
    const float* qz_b2  = (const float*)d_in[6];
    const float* zm_w   = (const float*)d_in[7];
    const float* zm_b   = (const float*)d_in[8];
    const float* zl_w   = (const float*)d_in[9];
    const float* zl_b   = (const float*)d_in[10];
    const float* gen_w1 = (const float*)d_in[11];
    const float* gen_w2 = (const float*)d_in[12];
    const float* gen_b2 = (const float*)d_in[13];
    const float* col_w  = (const float*)d_in[14];
    const float* col_b  = (const float*)d_in[15];

    float* out    = (float*)d_out;
    float* xmean  = out;                       // [B, D]
    float* z_out  = out + BB * DD;             // [B, L]
    float* zm_out = z_out + BB * LL;
    float* zl_out = zm_out + BB * LL;

    // Pack all fp16 weight images
    {
        int total = LL * RS + 2 * KCH * CHUNK_H + 32 * CHUNK_H + NP * ZWS;
        pack_weights<<<(total + 255) / 256, 256>>>(gen_w1, gen_w2, qz_w1,
                                                   qz_w2, zm_w, zl_w);
    }
    // enc1: h1 (fp16 mma)
    {
        cudaFuncSetAttribute(enc1_kernel,
                             cudaFuncAttributeMaxDynamicSharedMemorySize,
                             E1_SMEM);
        enc1_kernel<<<BB / 64, 512, E1_SMEM>>>(x, qz_b1);
    }
    // enc2 + heads fused
    {
        cudaFuncSetAttribute(enc2_heads_kernel,
                             cudaFuncAttributeMaxDynamicSharedMemorySize,
                             E2_SMEM);
        enc2_heads_kernel<<<BB / 64, 512, E2_SMEM>>>(eps, qz_b2, zm_b, zl_b,
                                                     z_out, zm_out, zl_out);
    }
    // decoder
    {
        cudaFuncSetAttribute(decoder_kernel,
                             cudaFuncAttributeMaxDynamicSharedMemorySize,
                             SMEM_TOTAL);
        dim3 grid(BB / MT, DD);
        decoder_kernel<<<grid, 512, SMEM_TOTAL>>>(Wmask, gen_b2, col_w, col_b,
                                                  xmean);
    }
}

// round 11
// speedup vs baseline: 1.4071x; 1.0751x over previous
#include <cuda_runtime.h>
#include <cuda_fp16.h>
#include <cuda_bf16.h>
#include <math.h>
#include <stdint.h>

// Problem constants
#define BB 512
#define DD 512
#define LL 32
#define HH 300
#define MT 128
#define NP 320
#define RS 328
#define ZS 40
#define NPAIR 10            // enc2 pair iterations
#define CHUNK_H (16 * RS)   // 5248 halves
#define CHUNK_B (CHUNK_H * 2)
#define CHUNK_U (CHUNK_B / 16)
#define PAIR_B  (2 * CHUNK_B)
#define TRIPLE_H (3 * CHUNK_H)
#define TRIPLE_B (3 * CHUNK_B)      // 31488
#define TRIPLE_U (3 * CHUNK_U)      // 1968
#define W1_U    (2 * CHUNK_U)

// Decoder SMEM layout (bytes)
#define SO_ZM   0                          // 10240
#define SO_G1   10240                      // 83968
#define SO_W1   94208                      // 20992
#define SO_RING 115200                     // 3 * 31488 = 94464
#define SO_B2   209664                     // 1280
#define SO_CW   210944                     // 1280
#define SO_OUT  212224                     // 512
#define SMEM_TOTAL 212736

// enc1 SMEM layout
#define XRS 520
#define SRS 72
#define SCH_B 2304          // 16*72*2
#define SCH_U 144           // units per slice-chunk (9 per row x 16 rows)
#define SPAIR_B 4608
#define SPAIR_U 288
#define E1_XS   0           // 64*520*2 = 66560
#define E1_RING 66560       // 4*4608 = 18432
#define E1_B1   84992       // 256
#define E1_SMEM 85248

// enc2 SMEM layout (unchanged)
#define E2_H1   0
#define E2_H2   41984
#define E2_RING 83968
#define E2_ZW   167936
#define E2_B2   214016
#define E2_ZB   215296
#define E2_SMEM 215808
#define ZWS 72

// ---------------------------------------------------------------------------
// Scratch (device globals: allocation-free rule)
// ---------------------------------------------------------------------------
__device__ float  g_z[BB * LL];
__device__ __half g_w1h[LL * RS];            // decoder W1
__device__ __half g_w2h[19 * CHUNK_H];       // decoder W2 (19 chunks)
__device__ __half g_ew1[32 * CHUNK_H];       // qz_w1 (32 chunks)
__device__ __half g_ew2[20 * CHUNK_H];       // qz_w2 (20 chunks, last zero)
__device__ __half g_zw[NP * ZWS];            // zm|zl
__device__ __half g_xh[BB * XRS];            // x fp16 padded
__device__ __half g_h1h[BB * RS];            // h1 fp16

// ---------------------------------------------------------------------------
// PTX helpers
// ---------------------------------------------------------------------------
__device__ __forceinline__ void ldsm_x4(uint32_t* r, uint32_t addr) {
    asm volatile("ldmatrix.sync.aligned.m8n8.x4.shared.b16 {%0,%1,%2,%3}, [%4];"
                 : "=r"(r[0]), "=r"(r[1]), "=r"(r[2]), "=r"(r[3]) : "r"(addr));
}
__device__ __forceinline__ void ldsm_x4t(uint32_t* r, uint32_t addr) {
    asm volatile("ldmatrix.sync.aligned.m8n8.x4.trans.shared.b16 {%0,%1,%2,%3}, [%4];"
                 : "=r"(r[0]), "=r"(r[1]), "=r"(r[2]), "=r"(r[3]) : "r"(addr));
}
__device__ __forceinline__ void mma16(float* d, const uint32_t* a, uint32_t b0, uint32_t b1) {
    asm volatile(
        "mma.sync.aligned.m16n8k16.row.col.f32.f16.f16.f32 "
        "{%0,%1,%2,%3}, {%4,%5,%6,%7}, {%8,%9}, {%0,%1,%2,%3};"
        : "+f"(d[0]), "+f"(d[1]), "+f"(d[2]), "+f"(d[3])
        : "r"(a[0]), "r"(a[1]), "r"(a[2]), "r"(a[3]), "r"(b0), "r"(b1));
}
__device__ __forceinline__ void cp16(uint32_t dst, const void* src) {
    asm volatile("cp.async.cg.shared.global [%0], [%1], 16;" :: "r"(dst), "l"(src));
}
__device__ __forceinline__ void cp_commit() {
    asm volatile("cp.async.commit_group;");
}

// ---------------------------------------------------------------------------
// Pack fp16 images: decoder W1/W2, enc W1/W2, heads weights, x
// ---------------------------------------------------------------------------
__global__ void pack_weights(const float* __restrict__ gen_w1,
                             const float* __restrict__ gen_w2,
                             const float* __restrict__ qz_w1,
                             const float* __restrict__ qz_w2,
                             const float* __restrict__ zm_w,
                             const float* __restrict__ zl_w,
                             const float* __restrict__ x) {
    int idx = blockIdx.x * blockDim.x + threadIdx.x;
    const int S0 = LL * RS;                 // 10496
    const int S1 = S0 + 19 * CHUNK_H;       // 110208
    const int S2 = S1 + 32 * CHUNK_H;       // 278144
    const int S3 = S2 + 20 * CHUNK_H;       // 383104
    const int S4 = S3 + NP * ZWS;           // 406144
    const int S5 = S4 + BB * XRS;           // 672384
    if (idx < S0) {
        int r = idx / RS, c = idx % RS;
        g_w1h[idx] = (c < HH) ? __float2half(gen_w1[r * HH + c]) : __half(0.f);
    } else if (idx < S1) {
        int i = idx - S0;
        int k = i / RS, c = i % RS;
        g_w2h[i] = (k < HH && c < HH) ? __float2half(gen_w2[k * HH + c]) : __half(0.f);
    } else if (idx < S2) {
        int i = idx - S1;
        int k = i / RS, c = i % RS;
        g_ew1[i] = (c < HH) ? __float2half(qz_w1[k * HH + c]) : __half(0.f);
    } else if (idx < S3) {
        int i = idx - S2;
        int k = i / RS, c = i % RS;
        g_ew2[i] = (k < HH && c < HH) ? __float2half(qz_w2[k * HH + c]) : __half(0.f);
    } else if (idx < S4) {
        int i = idx - S3;
        int k = i / ZWS, c = i % ZWS;
        float v = 0.f;
        if (k < HH) {
            if (c < 32) v = zm_w[k * LL + c];
            else if (c < 64) v = zl_w[k * LL + (c - 32)];
        }
        g_zw[i] = __float2half(v);
    } else if (idx < S5) {
        int i = idx - S4;
        int r = i / XRS, c = i % XRS;
        g_xh[i] = (c < DD) ? __float2half(x[r * DD + c]) : __half(0.f);
    }
}

// ---------------------------------------------------------------------------
// enc1: h1 = relu(x @ qz_w1 + b1). Grid (8 m-tiles, 5 n-slices of 64 cols).
// 256 threads, 2 CTAs/SM. 8 warps: warp&3 -> m16 stripe, warp>>2 -> nq (4 tiles)
// ---------------------------------------------------------------------------
__global__ void __launch_bounds__(256, 2)
enc1_kernel(const float* __restrict__ qz_b1) {
    extern __shared__ char smc[];
    float* b1s = (float*)(smc + E1_B1);
    const uint32_t xs_a   = (uint32_t)__cvta_generic_to_shared(smc + E1_XS);
    const uint32_t ring_a = (uint32_t)__cvta_generic_to_shared(smc + E1_RING);

    const int tid  = threadIdx.x;
    const int lane = tid & 31;
    const int warp = tid >> 5;
    const int ms   = (warp & 3) * 16;
    const int nq   = warp >> 2;            // 0..1
    const int m0   = blockIdx.x * 64;
    const int nc0  = blockIdx.y * 64;
    const int seg  = lane >> 3, rr = lane & 7;

    // prologue: xs (group), W pairs 0,1 (2 groups)
    {
        const __half* src = g_xh + m0 * XRS;
        for (int u = tid; u < 64 * XRS / 8; u += 256)
            cp16(xs_a + u * 16, src + u * 8);
        cp_commit();
        #pragma unroll
        for (int p = 0; p < 2; p++) {
            for (int u = tid; u < SPAIR_U; u += 256) {
                int ch = u / SCH_U, uu = u % SCH_U;
                int row = uu / 9, c16 = uu % 9;
                const __half* s = g_ew1 + ((p * 2 + ch) * 16 + row) * RS + nc0 + c16 * 8;
                cp16(ring_a + p * SPAIR_B + ch * SCH_B + (row * SRS + c16 * 8) * 2, s);
            }
            cp_commit();
        }
    }
    if (tid < 64) {
        int g = nc0 + tid;
        b1s[tid] = (g < HH) ? qz_b1[g] : 0.f;
    }
    asm volatile("cp.async.wait_group 2;");   // xs landed
    __syncthreads();

    const int a_ro = (seg & 1) * 8 + rr;
    const int a_cb = (seg >> 1) * 8;
    const int b_k  = (seg & 1) * 8 + rr;
    const int b_nb = (seg >> 1) * 8;

    float acc[4][4];
    #pragma unroll
    for (int t = 0; t < 4; t++)
        #pragma unroll
        for (int i = 0; i < 4; i++) acc[t][i] = 0.f;

    for (int ip = 0; ip < 16; ip++) {
        if (ip + 2 < 16) {
            for (int u = tid; u < SPAIR_U; u += 256) {
                int ch = u / SCH_U, uu = u % SCH_U;
                int row = uu / 9, c16 = uu % 9;
                const __half* s = g_ew1 + (((ip + 2) * 2 + ch) * 16 + row) * RS + nc0 + c16 * 8;
                cp16(ring_a + ((ip + 2) & 3) * SPAIR_B + ch * SCH_B + (row * SRS + c16 * 8) * 2, s);
            }
        }
        cp_commit();
        asm volatile("cp.async.wait_group 2;");
        __syncthreads();

        const uint32_t pbase = ring_a + (ip & 3) * SPAIR_B;
        #pragma unroll
        for (int q = 0; q < 2; q++) {
            const int kc = 2 * ip + q;
            uint32_t a[4];
            ldsm_x4(a, xs_a + ((ms + a_ro) * XRS + kc * 16 + a_cb) * 2);
            const uint32_t Bs = pbase + q * SCH_B;
            #pragma unroll
            for (int p2 = 0; p2 < 2; p2++) {
                int n0 = (nq * 4 + 2 * p2) * 8;
                uint32_t b[4];
                ldsm_x4t(b, Bs + (b_k * SRS + n0 + b_nb) * 2);
                mma16(acc[2 * p2],     a, b[0], b[1]);
                mma16(acc[2 * p2 + 1], a, b[2], b[3]);
            }
        }
    }

    // epilogue: relu(acc + b1) -> g_h1h
    {
        int row = ms + (lane >> 2);
        #pragma unroll
        for (int t = 0; t < 4; t++) {
            int cl = (nq * 4 + t) * 8 + 2 * (lane & 3);
            float v0 = fmaxf(acc[t][0] + b1s[cl], 0.f);
            float v1 = fmaxf(acc[t][1] + b1s[cl + 1], 0.f);
            float v2 = fmaxf(acc[t][2] + b1s[cl], 0.f);
            float v3 = fmaxf(acc[t][3] + b1s[cl + 1], 0.f);
            *(__half2*)(g_h1h + (m0 + row) * RS + nc0 + cl)     = __floats2half2_rn(v0, v1);
            *(__half2*)(g_h1h + (m0 + row + 8) * RS + nc0 + cl) = __floats2half2_rn(v2, v3);
        }
    }
}

// ---------------------------------------------------------------------------
// enc2 + heads fused (unchanged from R10)
// ---------------------------------------------------------------------------
__global__ void __launch_bounds__(512, 1)
enc2_heads_kernel(const float* __restrict__ eps,
                  const float* __restrict__ qz_b2,
                  const float* __restrict__ zm_b,
                  const float* __restrict__ zl_b,
                  float* __restrict__ z_out,
                  float* __restrict__ zm_out,
                  float* __restrict__ zl_out) {
    extern __shared__ char smc[];
    float* b2s = (float*)(smc + E2_B2);
    float* zbb = (float*)(smc + E2_ZB);
    float* zbuf = (float*)(smc + E2_RING);
    const uint32_t h1_a   = (uint32_t)__cvta_generic_to_shared(smc + E2_H1);
    const uint32_t h2_a   = (uint32_t)__cvta_generic_to_shared(smc + E2_H2);
    const uint32_t ring_a = (uint32_t)__cvta_generic_to_shared(smc + E2_RING);
    const uint32_t zw_a   = (uint32_t)__cvta_generic_to_shared(smc + E2_ZW);
    __half* h2s = (__half*)(smc + E2_H2);

    const int tid  = threadIdx.x;
    const int lane = tid & 31;
    const int warp = tid >> 5;
    const int ms   = (warp & 3) * 16;
    const int nq   = warp >> 2;
    const int m0   = blockIdx.x * 64;
    const int seg  = lane >> 3, rr = lane & 7;

    {
        const __half* h1src = g_h1h + m0 * RS;
        for (int u = tid; u < 64 * RS / 8; u += 512)
            cp16(h1_a + u * 16, h1src + u * 8);
        cp_commit();
        for (int u = tid; u < NP * ZWS / 8; u += 512)
            cp16(zw_a + u * 16, g_zw + u * 8);
        cp_commit();
        #pragma unroll
        for (int p = 0; p < 2; p++) {
            const __half* src = g_ew2 + p * 2 * CHUNK_H;
            for (int u = tid; u < 2 * CHUNK_U; u += 512)
                cp16(ring_a + p * PAIR_B + u * 16, src + u * 8);
            cp_commit();
        }
    }
    for (int c = tid; c < NP; c += 512)
        b2s[c] = (c < HH) ? qz_b2[c] : 0.f;
    if (tid < 32) zbb[tid] = zm_b[tid];
    else if (tid < 64) zbb[64 + tid - 32] = zl_b[tid - 32];

    asm volatile("cp.async.wait_group 2;");
    __syncthreads();

    const int a_ro = (seg & 1) * 8 + rr;
    const int a_cb = (seg >> 1) * 8;
    const int b_k  = (seg & 1) * 8 + rr;
    const int b_nb = (seg >> 1) * 8;

    float acc[10][4];
    #pragma unroll
    for (int t = 0; t < 10; t++)
        #pragma unroll
        for (int i = 0; i < 4; i++) acc[t][i] = 0.f;

    for (int ip = 0; ip < NPAIR; ip++) {
        if (ip + 2 < NPAIR) {
            const __half* src = g_ew2 + (ip + 2) * 2 * CHUNK_H;
            uint32_t dst = ring_a + ((ip + 2) & 3) * PAIR_B;
            for (int u = tid; u < 2 * CHUNK_U; u += 512)
                cp16(dst + u * 16, src + u * 8);
        }
        cp_commit();
        asm volatile("cp.async.wait_group 2;");
        __syncthreads();

        const uint32_t pbase = ring_a + (ip & 3) * PAIR_B;
        #pragma unroll
        for (int q = 0; q < 2; q++) {
            const int kc = 2 * ip + q;
            if (kc < 19) {
                const uint32_t Bs = pbase + q * CHUNK_B;
                uint32_t a[4];
                ldsm_x4(a, h1_a + ((ms + a_ro) * RS + kc * 16 + a_cb) * 2);
                #pragma unroll
                for (int p = 0; p < 5; p++) {
                    int n0 = (nq * 10 + 2 * p) * 8;
                    uint32_t b[4];
                    ldsm_x4t(b, Bs + (b_k * RS + n0 + b_nb) * 2);
                    mma16(acc[2 * p],     a, b[0], b[1]);
                    mma16(acc[2 * p + 1], a, b[2], b[3]);
                }
            }
        }
    }

    {
        int row = ms + (lane >> 2);
        #pragma unroll
        for (int t = 0; t < 10; t++) {
            int c = (nq * 10 + t) * 8 + 2 * (lane & 3);
            float v0 = fmaxf(acc[t][0] + b2s[c], 0.f);
            float v1 = fmaxf(acc[t][1] + b2s[c + 1], 0.f);
            float v2 = fmaxf(acc[t][2] + b2s[c], 0.f);
            float v3 = fmaxf(acc[t][3] + b2s[c + 1], 0.f);
            *(__half2*)(h2s + row * RS + c)       = __floats2half2_rn(v0, v1);
            *(__half2*)(h2s + (row + 8) * RS + c) = __floats2half2_rn(v2, v3);
        }
    }
    __syncthreads();

    float ah[2][4];
    #pragma unroll
    for (int t = 0; t < 2; t++)
        #pragma unroll
        for (int i = 0; i < 4; i++) ah[t][i] = 0.f;
    for (int ks = 0; ks < 19; ks++) {
        uint32_t a[4];
        ldsm_x4(a, h2_a + ((ms + a_ro) * RS + ks * 16 + a_cb) * 2);
        int n0 = nq * 16;
        uint32_t b[4];
        ldsm_x4t(b, zw_a + ((ks * 16 + b_k) * ZWS + n0 + b_nb) * 2);
        mma16(ah[0], a, b[0], b[1]);
        mma16(ah[1], a, b[2], b[3]);
    }
    __syncthreads();

    {
        int row = ms + (lane >> 2);
        #pragma unroll
        for (int t = 0; t < 2; t++) {
            int c = nq * 16 + t * 8 + 2 * (lane & 3);
            zbuf[row * 68 + c]           = ah[t][0];
            zbuf[row * 68 + c + 1]       = ah[t][1];
            zbuf[(row + 8) * 68 + c]     = ah[t][2];
            zbuf[(row + 8) * 68 + c + 1] = ah[t][3];
        }
    }
    __syncthreads();

    for (int i = tid; i < 64 * LL; i += 512) {
        int r = i >> 5, l = i & 31;
        float zm = zbuf[r * 68 + l] + zbb[l];
        float zl = zbuf[r * 68 + 32 + l] + zbb[64 + l];
        int o = (m0 + r) * LL + l;
        float zv = zm + eps[o] * expf(0.5f * zl);
        zm_out[o] = zm;
        zl_out[o] = zl;
        z_out[o]  = zv;
        g_z[o]    = zv;
    }
}

// ---------------------------------------------------------------------------
// Decoder: triple-chunk mainloop (6 triples + 1 tail chunk), ring of 3.
// ---------------------------------------------------------------------------
#define CHUNK_MMA(kc, Bs)                                                     \
    {                                                                         \
        uint32_t a[2][4];                                                     \
        _Pragma("unroll")                                                     \
        for (int m = 0; m < 2; m++)                                           \
            ldsm_x4(a[m], g1s_a + ((r0 + m * 16 + a_ro) * RS + (kc) * 16 + a_cb) * 2); \
        _Pragma("unroll")                                                     \
        for (int p = 0; p < 5; p++) {                                         \
            int n0 = (nq * 10 + 2 * p) * 8;                                   \
            uint32_t b[4];                                                    \
            ldsm_x4t(b, (Bs) + (b_k * RS + n0 + b_nb) * 2);                   \
            _Pragma("unroll")                                                 \
            for (int m = 0; m < 2; m++) {                                     \
                mma16(acc[m][2 * p],     a[m], b[0], b[1]);                   \
                mma16(acc[m][2 * p + 1], a[m], b[2], b[3]);                   \
            }                                                                 \
        }                                                                     \
    }

__global__ void __launch_bounds__(512, 1)
decoder_kernel(const float* __restrict__ Wmask,
               const float* __restrict__ gen_b2,
               const float* __restrict__ col_w,
               const float* __restrict__ col_b,
               float* __restrict__ xmean) {
    extern __shared__ char smc[];
    __half* Zms  = (__half*)(smc + SO_ZM);
    __half* G1s  = (__half*)(smc + SO_G1);
    float*  b2s  = (float*)(smc + SO_B2);
    float*  cws  = (float*)(smc + SO_CW);
    float*  outs = (float*)(smc + SO_OUT);

    const int tid  = threadIdx.x;
    const int lane = tid & 31;
    const int warp = tid >> 5;
    const int r0   = (warp & 3) * 32;
    const int nq   = warp >> 2;
    const int j    = blockIdx.y;
    const int b0   = blockIdx.x * MT;
    const int seg  = lane >> 3, rr = lane & 7;

    const uint32_t zms_a  = (uint32_t)__cvta_generic_to_shared(smc + SO_ZM);
    const uint32_t g1s_a  = (uint32_t)__cvta_generic_to_shared(smc + SO_G1);
    const uint32_t w1s_a  = (uint32_t)__cvta_generic_to_shared(smc + SO_W1);
    const uint32_t ring_a = (uint32_t)__cvta_generic_to_shared(smc + SO_RING);

    // prologue: W1 (group), triple 0 (group)
    {
        for (int u = tid; u < W1_U; u += 512)
            cp16(w1s_a + u * 16, g_w1h + u * 8);
        cp_commit();
        for (int u = tid; u < TRIPLE_U; u += 512)
            cp16(ring_a + u * 16, g_w2h + u * 8);
        cp_commit();
    }

    for (int idx = tid; idx < MT * LL; idx += 512) {
        int bl = idx >> 5, l = idx & 31;
        float v = g_z[(b0 + bl) * LL + l] * __ldg(Wmask + j * LL + l);
        Zms[bl * ZS + l] = __float2half(v);
    }
    for (int c = tid; c < NP; c += 512) {
        b2s[c] = (c < HH) ? __ldg(gen_b2 + c) : 0.f;
        cws[c] = (c < HH) ? __ldg(col_w + j * HH + c) : 0.f;
    }
    if (tid < MT) outs[tid] = 0.f;

    asm volatile("cp.async.wait_group 1;");   // W1 landed
    __syncthreads();

    const int a_ro = (seg & 1) * 8 + rr;
    const int a_cb = (seg >> 1) * 8;
    const int b_k  = (seg & 1) * 8 + rr;
    const int b_nb = (seg >> 1) * 8;

    float acc[2][10][4];
    #pragma unroll
    for (int m = 0; m < 2; m++)
        #pragma unroll
        for (int t = 0; t < 10; t++)
            #pragma unroll
            for (int i = 0; i < 4; i++) acc[m][t][i] = 0.f;

    // gemm1: G1 = relu(Zm @ W1)
    #pragma unroll
    for (int kk = 0; kk < 2; kk++) {
        uint32_t a[2][4];
        #pragma unroll
        for (int m = 0; m < 2; m++)
            ldsm_x4(a[m], zms_a + ((r0 + m * 16 + a_ro) * ZS + kk * 16 + a_cb) * 2);
        #pragma unroll
        for (int p = 0; p < 5; p++) {
            int n0 = (nq * 10 + 2 * p) * 8;
            uint32_t b[4];
            ldsm_x4t(b, w1s_a + ((kk * 16 + b_k) * RS + n0 + b_nb) * 2);
            #pragma unroll
            for (int m = 0; m < 2; m++) {
                mma16(acc[m][2 * p],     a[m], b[0], b[1]);
                mma16(acc[m][2 * p + 1], a[m], b[2], b[3]);
            }
        }
    }
    {
        #pragma unroll
        for (int m = 0; m < 2; m++) {
            int row = r0 + m * 16 + (lane >> 2);
            #pragma unroll
            for (int t = 0; t < 10; t++) {
                int c = (nq * 10 + t) * 8 + 2 * (lane & 3);
                __half2 lo = __floats2half2_rn(fmaxf(acc[m][t][0], 0.f), fmaxf(acc[m][t][1], 0.f));
                __half2 hi = __floats2half2_rn(fmaxf(acc[m][t][2], 0.f), fmaxf(acc[m][t][3], 0.f));
                *(__half2*)(G1s + row * RS + c)       = lo;
                *(__half2*)(G1s + (row + 8) * RS + c) = hi;
                acc[m][t][0] = acc[m][t][1] = acc[m][t][2] = acc[m][t][3] = 0.f;
            }
        }
    }
    __syncthreads();

    // mainloop: triples 0..5 (chunks 0..17), ring 3, prefetch dist 1
    for (int ip = 0; ip < 6; ip++) {
        if (ip < 5) {
            const __half* src = g_w2h + (ip + 1) * TRIPLE_H;
            uint32_t dst = ring_a + ((ip + 1) % 3) * TRIPLE_B;
            for (int u = tid; u < TRIPLE_U; u += 512)
                cp16(dst + u * 16, src + u * 8);
        } else {
            // tail chunk 18 -> slot 0 (occupant T3, consumed by barrier(4))
            const __half* src = g_w2h + 18 * CHUNK_H;
            for (int u = tid; u < CHUNK_U; u += 512)
                cp16(ring_a + u * 16, src + u * 8);
        }
        cp_commit();
        asm volatile("cp.async.wait_group 1;");   // triple ip landed
        __syncthreads();

        const uint32_t tb = ring_a + (ip % 3) * TRIPLE_B;
        CHUNK_MMA(3 * ip + 0, tb);
        CHUNK_MMA(3 * ip + 1, tb + CHUNK_B);
        CHUNK_MMA(3 * ip + 2, tb + 2 * CHUNK_B);
    }
    // tail: chunk 18
    asm volatile("cp.async.wait_group 0;");
    __syncthreads();
    CHUNK_MMA(18, ring_a);

    // epilogue
    #pragma unroll
    for (int m = 0; m < 2; m++) {
        float rs0 = 0.f, rs1 = 0.f;
        #pragma unroll
        for (int t = 0; t < 10; t++) {
            int cb = (nq * 10 + t) * 8 + 2 * (lane & 3);
            #pragma unroll
            for (int q = 0; q < 2; q++) {
                int c = cb + q;
                rs0 += fmaxf(acc[m][t][q] + b2s[c], 0.f) * cws[c];
                rs1 += fmaxf(acc[m][t][2 + q] + b2s[c], 0.f) * cws[c];
            }
        }
        rs0 += __shfl_xor_sync(0xffffffffu, rs0, 1);
        rs0 += __shfl_xor_sync(0xffffffffu, rs0, 2);
        rs1 += __shfl_xor_sync(0xffffffffu, rs1, 1);
        rs1 += __shfl_xor_sync(0xffffffffu, rs1, 2);
        if ((lane & 3) == 0) {
            int rbase = r0 + m * 16 + (lane >> 2);
            atomicAdd(&outs[rbase], rs0);
            atomicAdd(&outs[rbase + 8], rs1);
        }
    }
    __syncthreads();
    if (tid < MT) {
        xmean[(b0 + tid) * DD + j] = outs[tid] + __ldg(col_b + j);
    }
}

// ---------------------------------------------------------------------------
// Launch
// ---------------------------------------------------------------------------
extern "C" void kernel_launch(void* const* d_in, const int* in_sizes, int n_in,
                              void* d_out, int out_size) {
    const float* x      = (const float*)d_in[0];
    const float* eps    = (const float*)d_in[1];
    const float* Wmask  = (const float*)d_in[2];
    const float* qz_w1  = (const float*)d_in[3];
    const float* qz_b1  = (const float*)d_in[4];
    const float* qz_w2  = (const float*)d_in[5];
    const float* qz_b2  = (const float*)d_in[6];
    const float* zm_w   = (const float*)d_in[7];
    const float* zm_b   = (const float*)d_in[8];
    const float* zl_w   = (const float*)d_in[9];
    const float* zl_b   = (const float*)d_in[10];
    const float* gen_w1 = (const float*)d_in[11];
    const float* gen_w2 = (const float*)d_in[12];
    const float* gen_b2 = (const float*)d_in[13];
    const float* col_w  = (const float*)d_in[14];
    const float* col_b  = (const float*)d_in[15];

    float* out    = (float*)d_out;
    float* xmean  = out;
    float* z_out  = out + BB * DD;
    float* zm_out = z_out + BB * LL;
    float* zl_out = zm_out + BB * LL;

    // Pack fp16 images (weights + x)
    {
        int total = LL * RS + (19 + 32 + 20) * CHUNK_H + NP * ZWS + BB * XRS;
        pack_weights<<<(total + 255) / 256, 256>>>(gen_w1, gen_w2, qz_w1,
                                                   qz_w2, zm_w, zl_w, x);
    }
    // enc1 (n-split, 40 CTAs)
    {
        cudaFuncSetAttribute(enc1_kernel,
                             cudaFuncAttributeMaxDynamicSharedMemorySize,
                             E1_SMEM);
        dim3 grid(8, 5);
        enc1_kernel<<<grid, 256, E1_SMEM>>>(qz_b1);
    }
    // enc2 + heads fused
    {
        cudaFuncSetAttribute(enc2_heads_kernel,
                             cudaFuncAttributeMaxDynamicSharedMemorySize,
                             E2_SMEM);
        enc2_heads_kernel<<<BB / 64, 512, E2_SMEM>>>(eps, qz_b2, zm_b, zl_b,
                                                     z_out, zm_out, zl_out);
    }
    // decoder
    {
        cudaFuncSetAttribute(decoder_kernel,
                             cudaFuncAttributeMaxDynamicSharedMemorySize,
                             SMEM_TOTAL);
        dim3 grid(BB / MT, DD);
        decoder_kernel<<<grid, 512, SMEM_TOTAL>>>(Wmask, gen_b2, col_w, col_b,
                                                  xmean);
    }
}